// round 15
// baseline (speedup 1.0000x reference)
#include <cuda_runtime.h>

#define FFT_L   8192
#define NLAYERS 4
#define NSTATE  64
#define NROWS   4096
#define THREADS 512

// ---------------- static device tables ----------------
__device__ __align__(16) float2 g_tw[FFT_L];                        // W_N^k
__device__ __align__(16) float2 g_kraw[NLAYERS][FFT_L];             // raw K(omega_j)
__device__ __align__(16) float2 g_ke[NLAYERS][FFT_L];               // Hermitian kernel * (1/N)

// ---------------- complex helpers ----------------
__device__ __forceinline__ float2 cmul(float2 a, float2 b) {
    return make_float2(fmaf(a.x, b.x, -a.y * b.y), fmaf(a.x, b.y, a.y * b.x));
}
// a * conj(w), same 4-FMA cost
__device__ __forceinline__ float2 cmulc(float2 a, float2 w) {
    return make_float2(fmaf(a.x, w.x, a.y * w.y), fmaf(a.y, w.x, -a.x * w.y));
}
template <bool INV>
__device__ __forceinline__ float2 twm(float2 a, float2 w) {
    return INV ? cmulc(a, w) : cmul(a, w);
}
__device__ __forceinline__ float2 cadd(float2 a, float2 b) { return make_float2(a.x + b.x, a.y + b.y); }
__device__ __forceinline__ float2 csub(float2 a, float2 b) { return make_float2(a.x - b.x, a.y - b.y); }
template <bool INV>
__device__ __forceinline__ float2 mulj(float2 a) {   // * (-i) fwd, * (+i) inv
    return INV ? make_float2(-a.y, a.x) : make_float2(a.y, -a.x);
}

// pair-level bank swizzle: P indexes 16B pairs (elements 2P, 2P+1)
__device__ __forceinline__ int swp(int P) { return P ^ ((P >> 3) & 7); }
__device__ __forceinline__ float2 ld_elem(const float2* s, int i) {
    return s[(swp(i >> 1) << 1) | (i & 1)];
}
__device__ __forceinline__ float4 pack2(float2 a, float2 b) {
    return make_float4(a.x, a.y, b.x, b.y);
}

// ---------------- packed (f32x2) GELU: two independent lanes per call ----------------
typedef unsigned long long u64;
__device__ __forceinline__ u64 pk2(float x, float y) {
    u64 r; asm("mov.b64 %0, {%1, %2};" : "=l"(r) : "f"(x), "f"(y)); return r;
}
__device__ __forceinline__ u64 pkc(float x) { return pk2(x, x); }
__device__ __forceinline__ float2 upk(u64 a) {
    float2 r; asm("mov.b64 {%0, %1}, %2;" : "=f"(r.x), "=f"(r.y) : "l"(a)); return r;
}
__device__ __forceinline__ u64 f2fma(u64 a, u64 b, u64 c) {
    u64 r; asm("fma.rn.f32x2 %0, %1, %2, %3;" : "=l"(r) : "l"(a), "l"(b), "l"(c)); return r;
}
__device__ __forceinline__ u64 f2mul(u64 a, u64 b) {
    u64 r; asm("mul.rn.f32x2 %0, %1, %2;" : "=l"(r) : "l"(a), "l"(b)); return r;
}
__device__ __forceinline__ u64 f2add(u64 a, u64 b) {
    u64 r; asm("add.rn.f32x2 %0, %1, %2;" : "=l"(r) : "l"(a), "l"(b)); return r;
}

struct GeluC { u64 isq, a, one, p5, p4, p3, p2, p1, nl2e, half, mhalf; };
__device__ __forceinline__ GeluC gelu_consts() {
    GeluC c;
    c.isq  = pkc(0.70710678118654752f);
    c.a    = pkc(0.3275911f);
    c.one  = pkc(1.0f);
    c.p5   = pkc(1.061405429f);
    c.p4   = pkc(-1.453152027f);
    c.p3   = pkc(1.421413741f);
    c.p2   = pkc(-0.284496736f);
    c.p1   = pkc(0.254829592f);
    c.nl2e = pkc(-1.4426950408889634f);
    c.half = pkc(0.5f);
    c.mhalf= pkc(-0.5f);
    return c;
}

// gelu applied independently to s.x and s.y (A&S 7.1.26 erfc, branch-free)
__device__ __forceinline__ float2 gelu2(float2 s, const GeluC& c) {
    u64 v = pk2(s.x, s.y);
    u64 av; asm("and.b64 %0, %1, 0x7FFFFFFF7FFFFFFF;" : "=l"(av) : "l"(v));
    u64 z = f2mul(av, c.isq);
    u64 d = f2fma(z, c.a, c.one);
    float2 df = upk(d);
    float t0, t1;
    asm("rcp.approx.f32 %0, %1;" : "=f"(t0) : "f"(df.x));
    asm("rcp.approx.f32 %0, %1;" : "=f"(t1) : "f"(df.y));
    u64 t = pk2(t0, t1);
    u64 p = f2fma(c.p5, t, c.p4);
    p = f2fma(p, t, c.p3);
    p = f2fma(p, t, c.p2);
    p = f2fma(p, t, c.p1);
    p = f2mul(p, t);
    u64 m = f2mul(z, z);
    float2 wf = upk(f2mul(m, c.nl2e));    // -z^2 * log2(e)
    float e0, e1;
    asm("ex2.approx.f32 %0, %1;" : "=f"(e0) : "f"(wf.x));
    asm("ex2.approx.f32 %0, %1;" : "=f"(e1) : "f"(wf.y));
    u64 e = pk2(e0, e1);
    u64 h = f2mul(p, e);                  // erfc(z), z >= 0
    u64 q = f2fma(h, c.mhalf, c.half);    // 0.5 - 0.5*erfc
    u64 sg; asm("and.b64 %0, %1, 0x8000000080000000;" : "=l"(sg) : "l"(v));
    u64 qs; asm("xor.b64 %0, %1, %2;" : "=l"(qs) : "l"(q), "l"(sg));
    u64 phi = f2add(c.half, qs);          // v>=0: 1-0.5erfc ; v<0: 0.5erfc
    return upk(f2mul(v, phi));
}

// Chebyshev twiddle chain: w[k] = W^{k+1}
__device__ __forceinline__ void chain7(float2 w1, float2 w[7]) {
    float twoc = 2.0f * w1.x;
    w[0] = w1;
    w[1] = make_float2(fmaf(twoc, w1.x, -1.0f), twoc * w1.y);
#pragma unroll
    for (int k = 2; k < 7; ++k)
        w[k] = make_float2(fmaf(twoc, w[k - 1].x, -w[k - 2].x),
                           fmaf(twoc, w[k - 1].y, -w[k - 2].y));
}

// ---------------- DFT-8 / DFT-16 in registers ----------------
template <bool INV>
__device__ __forceinline__ void dft8(float2 a[8]) {
    const float CC = 0.70710678118654752f;
    float2 s0 = cadd(a[0], a[4]), s1 = csub(a[0], a[4]);
    float2 s2 = cadd(a[2], a[6]), s3 = mulj<INV>(csub(a[2], a[6]));
    float2 E0 = cadd(s0, s2), E2 = csub(s0, s2);
    float2 E1 = cadd(s1, s3), E3 = csub(s1, s3);
    float2 t0 = cadd(a[1], a[5]), t1 = csub(a[1], a[5]);
    float2 t2 = cadd(a[3], a[7]), t3 = mulj<INV>(csub(a[3], a[7]));
    float2 O0 = cadd(t0, t2), O2 = csub(t0, t2);
    float2 O1 = cadd(t1, t3), O3 = csub(t1, t3);
    float2 O1w = INV ? make_float2(CC * (O1.x - O1.y), CC * (O1.x + O1.y))
                     : make_float2(CC * (O1.x + O1.y), CC * (O1.y - O1.x));
    float2 O2w = mulj<INV>(O2);
    float2 O3w = INV ? make_float2(-CC * (O3.x + O3.y), CC * (O3.x - O3.y))
                     : make_float2(CC * (O3.y - O3.x), -CC * (O3.x + O3.y));
    a[0] = cadd(E0, O0);  a[4] = csub(E0, O0);
    a[1] = cadd(E1, O1w); a[5] = csub(E1, O1w);
    a[2] = cadd(E2, O2w); a[6] = csub(E2, O2w);
    a[3] = cadd(E3, O3w); a[7] = csub(E3, O3w);
}

template <bool INV>
__device__ __forceinline__ void dft16(const float2 a[16], float2 X[16]) {
    float2 E[8] = {a[0], a[2], a[4], a[6], a[8], a[10], a[12], a[14]};
    float2 O[8] = {a[1], a[3], a[5], a[7], a[9], a[11], a[13], a[15]};
    dft8<INV>(E);
    dft8<INV>(O);
    const float c1 = 0.9238795325112867f, s1 = 0.3826834323650898f,
                SQ = 0.7071067811865476f;
    const float sg = INV ? 1.0f : -1.0f;
    { float2 t = O[0];            X[0] = cadd(E[0], t); X[8]  = csub(E[0], t); }
    { float2 t = mulj<INV>(O[4]); X[4] = cadd(E[4], t); X[12] = csub(E[4], t); }
    float2 W1 = make_float2(c1, sg * s1);
    float2 W2 = make_float2(SQ, sg * SQ);
    float2 W3 = make_float2(s1, sg * c1);
    float2 W5 = make_float2(-s1, sg * c1);
    float2 W6 = make_float2(-SQ, sg * SQ);
    float2 W7 = make_float2(-c1, sg * s1);
    { float2 t = cmul(O[1], W1); X[1] = cadd(E[1], t); X[9]  = csub(E[1], t); }
    { float2 t = cmul(O[2], W2); X[2] = cadd(E[2], t); X[10] = csub(E[2], t); }
    { float2 t = cmul(O[3], W3); X[3] = cadd(E[3], t); X[11] = csub(E[3], t); }
    { float2 t = cmul(O[5], W5); X[5] = cadd(E[5], t); X[13] = csub(E[5], t); }
    { float2 t = cmul(O[6], W6); X[6] = cadd(E[6], t); X[14] = csub(E[6], t); }
    { float2 t = cmul(O[7], W7); X[7] = cadd(E[7], t); X[15] = csub(E[7], t); }
}

// ---------------- prologue kernels ----------------
__global__ void init_tw_kernel() {
    int j = blockIdx.x * blockDim.x + threadIdx.x;
    if (j < FFT_L) {
        float s, c;
        sincospif(-(float)j / (float)(FFT_L / 2), &s, &c);
        g_tw[j] = make_float2(c, s);
    }
}

__global__ void compute_k_kernel(const float* __restrict__ Lr, const float* __restrict__ Li,
                                 const float* __restrict__ P,  const float* __restrict__ B,
                                 const float* __restrict__ Ct, const float* __restrict__ step) {
    int gid = blockIdx.x * blockDim.x + threadIdx.x;
    if (gid >= NLAYERS * FFT_L) return;
    int layer = gid >> 13;
    int j     = gid & (FFT_L - 1);
    const float* lr = Lr + layer * NSTATE;
    const float* li = Li + layer * NSTATE;
    const float* Pp = P  + layer * NSTATE;
    const float* Bp = B  + layer * NSTATE;
    const float* Cp = Ct + layer * NSTATE;
    float st = step[layer];

    float ang = (-6.2831855f * (float)j) / 8192.0f;
    float s, c;
    sincosf(ang, &s, &c);
    float opr = 1.0f + c, opi = s;
    float omr = 1.0f - c, omi = -s;
    float inv_p2 = 1.0f / (opr * opr + opi * opi);
    float qr = (omr * opr + omi * opi) * inv_p2;
    float qi = (omi * opr - omr * opi) * inv_p2;
    float gsc = 2.0f / st;
    float gr = gsc * qr, gi = gsc * qi;
    float cr = 2.0f * opr * inv_p2, ci = -2.0f * opi * inv_p2;

    float k00r = 0.f, k00i = 0.f, k01r = 0.f, k01i = 0.f;
    float k10r = 0.f, k10i = 0.f, k11r = 0.f, k11i = 0.f;
#pragma unroll 8
    for (int n = 0; n < NSTATE; n++) {
        float dr = gr - lr[n];
        float di = gi - li[n];
        float inv = 1.0f / (dr * dr + di * di);
        float ir = dr * inv, ii = -di * inv;
        float b = Bp[n], p = Pp[n], ct = Cp[n];
        float v00 = ct * b, v01 = ct * p, v10 = p * b, v11 = p * p;
        k00r += v00 * ir; k00i += v00 * ii;
        k01r += v01 * ir; k01i += v01 * ii;
        k10r += v10 * ir; k10i += v10 * ii;
        k11r += v11 * ir; k11i += v11 * ii;
    }
    float d1r = 1.0f + k11r, d1i = k11i;
    float invd1 = 1.0f / (d1r * d1r + d1i * d1i);
    float numr = k01r * k10r - k01i * k10i;
    float numi = k01r * k10i + k01i * k10r;
    float qr2 = (numr * d1r + numi * d1i) * invd1;
    float qi2 = (numi * d1r - numr * d1i) * invd1;
    float tr = k00r - qr2, ti = k00i - qi2;
    g_kraw[layer][j] = make_float2(cr * tr - ci * ti, cr * ti + ci * tr);
}

__global__ void symmetrize_k_kernel() {
    int gid = blockIdx.x * blockDim.x + threadIdx.x;
    if (gid >= NLAYERS * FFT_L) return;
    int layer = gid >> 13;
    int j     = gid & (FFT_L - 1);
    float2 K1 = g_kraw[layer][j];
    float2 K2 = g_kraw[layer][(FFT_L - j) & (FFT_L - 1)];
    const float sc = 0.5f / (float)FFT_L;   // Hermitian part * 1/N
    g_ke[layer][j] = make_float2((K1.x + K2.x) * sc, (K1.y - K2.y) * sc);
}

// ---------------- T=0 twiddle+store for layer-0 F1 (butterflies 2t, 2t+1) ----------------
__device__ __forceinline__ void store0_fwd(float4* __restrict__ dst, float2 a[8], float2 b[8],
                                           const float2* __restrict__ s_tw, int t) {
    float4 w01 = *(const float4*)&s_tw[t << 1];
    float2 wA[7], wB[7];
    chain7(make_float2(w01.x, w01.y), wA);
    chain7(make_float2(w01.z, w01.w), wB);
    int Pb = t << 3;
    dst[swp(Pb + 0)] = pack2(a[0],              cmul(a[1], wA[0]));
    dst[swp(Pb + 1)] = pack2(cmul(a[2], wA[1]), cmul(a[3], wA[2]));
    dst[swp(Pb + 2)] = pack2(cmul(a[4], wA[3]), cmul(a[5], wA[4]));
    dst[swp(Pb + 3)] = pack2(cmul(a[6], wA[5]), cmul(a[7], wA[6]));
    dst[swp(Pb + 4)] = pack2(b[0],              cmul(b[1], wB[0]));
    dst[swp(Pb + 5)] = pack2(cmul(b[2], wB[1]), cmul(b[3], wB[2]));
    dst[swp(Pb + 6)] = pack2(cmul(b[4], wB[3]), cmul(b[5], wB[4]));
    dst[swp(Pb + 7)] = pack2(cmul(b[6], wB[5]), cmul(b[7], wB[6]));
}

// ---------------- T=0 dual-butterfly store (butterflies t and t+512) ----------------
template <bool INV>
__device__ __forceinline__ void dual_bfly_store(float4* __restrict__ dst,
                                                float2 ai[8], float2 bi[8],
                                                const float2* __restrict__ s_tw, int t) {
    float2 w1a = s_tw[t], w1b = s_tw[t + 512];
    if (INV) { w1a.y = -w1a.y; w1b.y = -w1b.y; }
    float2 wA[7], wB[7];
    chain7(w1a, wA);
    chain7(w1b, wB);
    int Pa = t << 2;               // pairs for elements 8t .. 8t+7
    dst[swp(Pa + 0)] = pack2(ai[0],              cmul(ai[1], wA[0]));
    dst[swp(Pa + 1)] = pack2(cmul(ai[2], wA[1]), cmul(ai[3], wA[2]));
    dst[swp(Pa + 2)] = pack2(cmul(ai[4], wA[3]), cmul(ai[5], wA[4]));
    dst[swp(Pa + 3)] = pack2(cmul(ai[6], wA[5]), cmul(ai[7], wA[6]));
    int Pb = Pa + 2048;            // pairs for elements 8(t+512) .. +7
    dst[swp(Pb + 0)] = pack2(bi[0],              cmul(bi[1], wB[0]));
    dst[swp(Pb + 1)] = pack2(cmul(bi[2], wB[1]), cmul(bi[3], wB[2]));
    dst[swp(Pb + 2)] = pack2(cmul(bi[4], wB[3]), cmul(bi[5], wB[4]));
    dst[swp(Pb + 3)] = pack2(cmul(bi[6], wB[5]), cmul(bi[7], wB[6]));
}

// ---------------- generic radix-8 pass for T in {3, 6}: smem twiddle TABLE ----------------
// tbl rows padded to 5 float4 (bank-spread); row r holds W^{8r·k} (T=3) / W^{64r·k} (T=6), k=1..7.
template <bool INV, int T>
__device__ __forceinline__ void r8_pass(const float4* __restrict__ src,
                                        float4* __restrict__ dst,
                                        const float4* __restrict__ tbl) {
    int t = threadIdx.x;
    float2 a[8], b[8];
#pragma unroll
    for (int j = 0; j < 8; ++j) {
        float4 v = src[swp(t + 512 * j)];
        a[j] = make_float2(v.x, v.y);
        b[j] = make_float2(v.z, v.w);
    }
    dft8<INV>(a);
    dft8<INV>(b);
    int idx = t << 1;
    int pT = idx & ~((1 << T) - 1);
    int qA = idx & ((1 << T) - 1);
    const float4* r = tbl + (pT >> T) * 5;
    float4 r0 = r[0], r1 = r[1], r2 = r[2], r3 = r[3];
    float2 w[7] = { make_float2(r0.x, r0.y), make_float2(r0.z, r0.w),
                    make_float2(r1.x, r1.y), make_float2(r1.z, r1.w),
                    make_float2(r2.x, r2.y), make_float2(r2.z, r2.w),
                    make_float2(r3.x, r3.y) };
    int Pb = (qA >> 1) + (pT << 2);
    const int S = 1 << (T - 1);
    dst[swp(Pb + 0 * S)] = pack2(a[0], b[0]);
#pragma unroll
    for (int k = 1; k < 8; ++k)
        dst[swp(Pb + k * S)] = pack2(twm<INV>(a[k], w[k - 1]), twm<INV>(b[k], w[k - 1]));
}

// ---------------- fused 4-layer block kernel ----------------
__global__ void __launch_bounds__(THREADS, 1)
ssm_block_kernel(const float* __restrict__ in, float* __restrict__ out) {
    extern __shared__ float4 smem4[];
    float4* X4 = smem4;                          // 4096 pairs, swizzled
    float4* Y4 = smem4 + 4096;                   // 4096 pairs, swizzled
    float4* U4 = smem4 + 8192;                   // residual, plain pair layout
    float2* s_tw = (float2*)(smem4 + 12288);     // 1024-entry twiddle cache (8 KB)
    float4* s_t3 = smem4 + 12800;                // 128 rows x 5 float4 (10 KB)
    float4* s_t6 = smem4 + 13440;                // 16 rows x 5 float4 (1.25 KB)

    size_t row = (size_t)blockIdx.x * 2;
    const float* in0 = in + row * FFT_L;
    const float* in1 = in + (row + 1) * FFT_L;
    float* o0 = out + row * FFT_L;
    float* o1 = out + (row + 1) * FFT_L;
    int t = threadIdx.x;

    // twiddle caches: entries 2t,2t+1 (used by F1 same-thread), plus T3/T6 chain tables
    *(float4*)&s_tw[t << 1] = *(const float4*)&g_tw[t << 1];
    if (t < 144) {
        int isT6 = (t >= 128) ? 1 : 0;
        int rrow = isT6 ? (t - 128) : t;
        float2 w1 = g_tw[rrow << (isT6 ? 6 : 3)];
        float2 w[7];
        chain7(w1, w);
        float4* r = (isT6 ? s_t6 : s_t3) + rrow * 5;
        r[0] = make_float4(w[0].x, w[0].y, w[1].x, w[1].y);
        r[1] = make_float4(w[2].x, w[2].y, w[3].x, w[3].y);
        r[2] = make_float4(w[4].x, w[4].y, w[5].x, w[5].y);
        r[3] = make_float4(w[6].x, w[6].y, 0.f, 0.f);
    }

    // ---- layer-0 F1: radix-8 (T=0) from gmem; stash residual pairs in U ----
    {
        float2 a[8], b[8];
#pragma unroll
        for (int j = 0; j < 8; ++j) {
            int i = (t << 1) + 1024 * j;
            float2 va = *(const float2*)(in0 + i);
            float2 vb = *(const float2*)(in1 + i);
            a[j] = make_float2(va.x, vb.x);
            b[j] = make_float2(va.y, vb.y);
            U4[t + 512 * j] = make_float4(va.x, vb.x, va.y, vb.y);
        }
        dft8<false>(a);
        dft8<false>(b);
        store0_fwd(X4, a, b, s_tw, t);
    }
    __syncthreads();

    for (int layer = 0; layer < NLAYERS; ++layer) {
        r8_pass<false, 3>(X4, Y4, s_t3); __syncthreads();
        r8_pass<false, 6>(Y4, X4, s_t6); __syncthreads();

        // ---- MID: F4 (radix-16) -> filter -> I1 (two inverse radix-8, T=0), X -> Y ----
        {
            const float2* Xs = (const float2*)X4;
            const float2* __restrict__ ke = g_ke[layer];
            float2 a[16], S[16];
#pragma unroll
            for (int j = 0; j < 16; ++j) a[j] = ld_elem(Xs, t + (j << 9));
            dft16<false>(a, S);
#pragma unroll
            for (int k = 0; k < 16; ++k) S[k] = cmul(S[k], ke[t + (k << 9)]);
            float2 ai[8], bi[8];
#pragma unroll
            for (int j = 0; j < 8; ++j) {
                ai[j] = S[2 * j];
                bi[j] = S[2 * j + 1];
            }
            dft8<true>(ai);
            dft8<true>(bi);
            dual_bfly_store<true>(Y4, ai, bi, s_tw, t);
        }
        __syncthreads();

        r8_pass<true, 3>(Y4, X4, s_t3); __syncthreads();
        r8_pass<true, 6>(X4, Y4, s_t6); __syncthreads();

        if (layer < NLAYERS - 1) {
            // ---- BOUNDARY: I4 (radix-16 inv) + residual/GELU (U r/w) + next F1, Y -> X ----
            const float2* Ys = (const float2*)Y4;
            float2* Ue = (float2*)U4;
            float2 a[16], Xo[16];
#pragma unroll
            for (int j = 0; j < 16; ++j) a[j] = ld_elem(Ys, t + (j << 9));
            dft16<true>(a, Xo);
            GeluC gc = gelu_consts();
            float2 v[16];
#pragma unroll
            for (int k = 0; k < 16; ++k) {
                int i = t + (k << 9);
                float2 u = Ue[i];                    // same thread wrote element i
                v[k] = gelu2(cadd(Xo[k], u), gc);
                Ue[i] = v[k];                        // next layer's residual
            }
            float2 ai[8], bi[8];
#pragma unroll
            for (int j = 0; j < 8; ++j) {
                ai[j] = v[2 * j];
                bi[j] = v[2 * j + 1];
            }
            dft8<false>(ai);
            dft8<false>(bi);
            dual_bfly_store<false>(X4, ai, bi, s_tw, t);
            __syncthreads();
        } else {
            // ---- final I4: radix-16 inv + residual + GELU -> gmem ----
            const float2* Ys = (const float2*)Y4;
            const float2* Ue = (const float2*)U4;
            float2 a[16], Xo[16];
#pragma unroll
            for (int j = 0; j < 16; ++j) a[j] = ld_elem(Ys, t + (j << 9));
            dft16<true>(a, Xo);
            GeluC gc = gelu_consts();
#pragma unroll
            for (int k = 0; k < 16; ++k) {
                int i = t + (k << 9);
                float2 res = gelu2(cadd(Xo[k], Ue[i]), gc);
                o0[i] = res.x;
                o1[i] = res.y;
            }
        }
    }
}

// ---------------- launch ----------------
extern "C" void kernel_launch(void* const* d_in, const int* in_sizes, int n_in,
                              void* d_out, int out_size) {
    const float* u  = (const float*)d_in[0];
    const float* Lr = (const float*)d_in[1];
    const float* Li = (const float*)d_in[2];
    const float* P  = (const float*)d_in[3];
    const float* B  = (const float*)d_in[4];
    const float* Ct = (const float*)d_in[5];
    const float* st = (const float*)d_in[6];
    float* out = (float*)d_out;

    // 12288 data pairs + 512 (s_tw) + 640 (s_t3) + 80 (s_t6) float4
    const size_t smem_bytes = (size_t)(13520) * sizeof(float4);   // 211.25 KB
    cudaFuncSetAttribute(ssm_block_kernel,
                         cudaFuncAttributeMaxDynamicSharedMemorySize, (int)smem_bytes);

    init_tw_kernel<<<FFT_L / 256, 256>>>();
    compute_k_kernel<<<(NLAYERS * FFT_L) / 256, 256>>>(Lr, Li, P, B, Ct, st);
    symmetrize_k_kernel<<<(NLAYERS * FFT_L) / 256, 256>>>();

    ssm_block_kernel<<<NROWS / 2, THREADS, smem_bytes>>>(u, out);
}

// round 16
// speedup vs baseline: 1.0189x; 1.0189x over previous
#include <cuda_runtime.h>

#define FFT_L   8192
#define NLAYERS 4
#define NSTATE  64
#define NROWS   4096
#define THREADS 512

// ---------------- static device tables ----------------
__device__ __align__(16) float2 g_tw[FFT_L];                        // W_N^k
__device__ __align__(16) float2 g_kraw[NLAYERS][FFT_L];             // raw K(omega_j)
__device__ __align__(16) float2 g_ke[NLAYERS][FFT_L];               // Hermitian kernel * (1/N)

// ---------------- complex helpers ----------------
__device__ __forceinline__ float2 cmul(float2 a, float2 b) {
    return make_float2(fmaf(a.x, b.x, -a.y * b.y), fmaf(a.x, b.y, a.y * b.x));
}
__device__ __forceinline__ float2 cadd(float2 a, float2 b) { return make_float2(a.x + b.x, a.y + b.y); }
__device__ __forceinline__ float2 csub(float2 a, float2 b) { return make_float2(a.x - b.x, a.y - b.y); }
template <bool INV>
__device__ __forceinline__ float2 mulj(float2 a) {   // * (-i) fwd, * (+i) inv
    return INV ? make_float2(-a.y, a.x) : make_float2(a.y, -a.x);
}

// pair-level bank swizzle: P indexes 16B pairs (elements 2P, 2P+1)
__device__ __forceinline__ int swp(int P) { return P ^ ((P >> 3) & 7); }
__device__ __forceinline__ float2 ld_elem(const float2* s, int i) {
    return s[(swp(i >> 1) << 1) | (i & 1)];
}
__device__ __forceinline__ float4 pack2(float2 a, float2 b) {
    return make_float4(a.x, a.y, b.x, b.y);
}

// ---------------- packed (f32x2) GELU: two independent lanes per call ----------------
typedef unsigned long long u64;
__device__ __forceinline__ u64 pk2(float x, float y) {
    u64 r; asm("mov.b64 %0, {%1, %2};" : "=l"(r) : "f"(x), "f"(y)); return r;
}
__device__ __forceinline__ u64 pkc(float x) { return pk2(x, x); }
__device__ __forceinline__ float2 upk(u64 a) {
    float2 r; asm("mov.b64 {%0, %1}, %2;" : "=f"(r.x), "=f"(r.y) : "l"(a)); return r;
}
__device__ __forceinline__ u64 f2fma(u64 a, u64 b, u64 c) {
    u64 r; asm("fma.rn.f32x2 %0, %1, %2, %3;" : "=l"(r) : "l"(a), "l"(b), "l"(c)); return r;
}
__device__ __forceinline__ u64 f2mul(u64 a, u64 b) {
    u64 r; asm("mul.rn.f32x2 %0, %1, %2;" : "=l"(r) : "l"(a), "l"(b)); return r;
}
__device__ __forceinline__ u64 f2add(u64 a, u64 b) {
    u64 r; asm("add.rn.f32x2 %0, %1, %2;" : "=l"(r) : "l"(a), "l"(b)); return r;
}

struct GeluC { u64 isq, a, one, p5, p4, p3, p2, p1, nl2e, half, mhalf; };
__device__ __forceinline__ GeluC gelu_consts() {
    GeluC c;
    c.isq  = pkc(0.70710678118654752f);
    c.a    = pkc(0.3275911f);
    c.one  = pkc(1.0f);
    c.p5   = pkc(1.061405429f);
    c.p4   = pkc(-1.453152027f);
    c.p3   = pkc(1.421413741f);
    c.p2   = pkc(-0.284496736f);
    c.p1   = pkc(0.254829592f);
    c.nl2e = pkc(-1.4426950408889634f);
    c.half = pkc(0.5f);
    c.mhalf= pkc(-0.5f);
    return c;
}

// gelu applied independently to s.x and s.y (A&S 7.1.26 erfc, branch-free)
__device__ __forceinline__ float2 gelu2(float2 s, const GeluC& c) {
    u64 v = pk2(s.x, s.y);
    u64 av; asm("and.b64 %0, %1, 0x7FFFFFFF7FFFFFFF;" : "=l"(av) : "l"(v));
    u64 z = f2mul(av, c.isq);
    u64 d = f2fma(z, c.a, c.one);
    float2 df = upk(d);
    float t0, t1;
    asm("rcp.approx.f32 %0, %1;" : "=f"(t0) : "f"(df.x));
    asm("rcp.approx.f32 %0, %1;" : "=f"(t1) : "f"(df.y));
    u64 t = pk2(t0, t1);
    u64 p = f2fma(c.p5, t, c.p4);
    p = f2fma(p, t, c.p3);
    p = f2fma(p, t, c.p2);
    p = f2fma(p, t, c.p1);
    p = f2mul(p, t);
    u64 m = f2mul(z, z);
    float2 wf = upk(f2mul(m, c.nl2e));    // -z^2 * log2(e)
    float e0, e1;
    asm("ex2.approx.f32 %0, %1;" : "=f"(e0) : "f"(wf.x));
    asm("ex2.approx.f32 %0, %1;" : "=f"(e1) : "f"(wf.y));
    u64 e = pk2(e0, e1);
    u64 h = f2mul(p, e);                  // erfc(z), z >= 0
    u64 q = f2fma(h, c.mhalf, c.half);    // 0.5 - 0.5*erfc
    u64 sg; asm("and.b64 %0, %1, 0x8000000080000000;" : "=l"(sg) : "l"(v));
    u64 qs; asm("xor.b64 %0, %1, %2;" : "=l"(qs) : "l"(q), "l"(sg));
    u64 phi = f2add(c.half, qs);          // v>=0: 1-0.5erfc ; v<0: 0.5erfc
    return upk(f2mul(v, phi));
}

// Chebyshev twiddle chain: w[k] = W^{k+1}, built via W^{k+1} = 2cos(th)*W^k - W^{k-1}
__device__ __forceinline__ void chain7(float2 w1, float2 w[7]) {
    float twoc = 2.0f * w1.x;
    w[0] = w1;
    w[1] = make_float2(fmaf(twoc, w1.x, -1.0f), twoc * w1.y);
#pragma unroll
    for (int k = 2; k < 7; ++k)
        w[k] = make_float2(fmaf(twoc, w[k - 1].x, -w[k - 2].x),
                           fmaf(twoc, w[k - 1].y, -w[k - 2].y));
}

// ---------------- DFT-8 / DFT-16 in registers ----------------
template <bool INV>
__device__ __forceinline__ void dft8(float2 a[8]) {
    const float CC = 0.70710678118654752f;
    float2 s0 = cadd(a[0], a[4]), s1 = csub(a[0], a[4]);
    float2 s2 = cadd(a[2], a[6]), s3 = mulj<INV>(csub(a[2], a[6]));
    float2 E0 = cadd(s0, s2), E2 = csub(s0, s2);
    float2 E1 = cadd(s1, s3), E3 = csub(s1, s3);
    float2 t0 = cadd(a[1], a[5]), t1 = csub(a[1], a[5]);
    float2 t2 = cadd(a[3], a[7]), t3 = mulj<INV>(csub(a[3], a[7]));
    float2 O0 = cadd(t0, t2), O2 = csub(t0, t2);
    float2 O1 = cadd(t1, t3), O3 = csub(t1, t3);
    float2 O1w = INV ? make_float2(CC * (O1.x - O1.y), CC * (O1.x + O1.y))
                     : make_float2(CC * (O1.x + O1.y), CC * (O1.y - O1.x));
    float2 O2w = mulj<INV>(O2);
    float2 O3w = INV ? make_float2(-CC * (O3.x + O3.y), CC * (O3.x - O3.y))
                     : make_float2(CC * (O3.y - O3.x), -CC * (O3.x + O3.y));
    a[0] = cadd(E0, O0);  a[4] = csub(E0, O0);
    a[1] = cadd(E1, O1w); a[5] = csub(E1, O1w);
    a[2] = cadd(E2, O2w); a[6] = csub(E2, O2w);
    a[3] = cadd(E3, O3w); a[7] = csub(E3, O3w);
}

template <bool INV>
__device__ __forceinline__ void dft16(const float2 a[16], float2 X[16]) {
    float2 E[8] = {a[0], a[2], a[4], a[6], a[8], a[10], a[12], a[14]};
    float2 O[8] = {a[1], a[3], a[5], a[7], a[9], a[11], a[13], a[15]};
    dft8<INV>(E);
    dft8<INV>(O);
    const float c1 = 0.9238795325112867f, s1 = 0.3826834323650898f,
                SQ = 0.7071067811865476f;
    const float sg = INV ? 1.0f : -1.0f;
    { float2 t = O[0];            X[0] = cadd(E[0], t); X[8]  = csub(E[0], t); }
    { float2 t = mulj<INV>(O[4]); X[4] = cadd(E[4], t); X[12] = csub(E[4], t); }
    float2 W1 = make_float2(c1, sg * s1);
    float2 W2 = make_float2(SQ, sg * SQ);
    float2 W3 = make_float2(s1, sg * c1);
    float2 W5 = make_float2(-s1, sg * c1);
    float2 W6 = make_float2(-SQ, sg * SQ);
    float2 W7 = make_float2(-c1, sg * s1);
    { float2 t = cmul(O[1], W1); X[1] = cadd(E[1], t); X[9]  = csub(E[1], t); }
    { float2 t = cmul(O[2], W2); X[2] = cadd(E[2], t); X[10] = csub(E[2], t); }
    { float2 t = cmul(O[3], W3); X[3] = cadd(E[3], t); X[11] = csub(E[3], t); }
    { float2 t = cmul(O[5], W5); X[5] = cadd(E[5], t); X[13] = csub(E[5], t); }
    { float2 t = cmul(O[6], W6); X[6] = cadd(E[6], t); X[14] = csub(E[6], t); }
    { float2 t = cmul(O[7], W7); X[7] = cadd(E[7], t); X[15] = csub(E[7], t); }
}

// ---------------- prologue kernels ----------------
__global__ void init_tw_kernel() {
    int j = blockIdx.x * blockDim.x + threadIdx.x;
    if (j < FFT_L) {
        float s, c;
        sincospif(-(float)j / (float)(FFT_L / 2), &s, &c);
        g_tw[j] = make_float2(c, s);
    }
}

__global__ void compute_k_kernel(const float* __restrict__ Lr, const float* __restrict__ Li,
                                 const float* __restrict__ P,  const float* __restrict__ B,
                                 const float* __restrict__ Ct, const float* __restrict__ step) {
    int gid = blockIdx.x * blockDim.x + threadIdx.x;
    if (gid >= NLAYERS * FFT_L) return;
    int layer = gid >> 13;
    int j     = gid & (FFT_L - 1);
    const float* lr = Lr + layer * NSTATE;
    const float* li = Li + layer * NSTATE;
    const float* Pp = P  + layer * NSTATE;
    const float* Bp = B  + layer * NSTATE;
    const float* Cp = Ct + layer * NSTATE;
    float st = step[layer];

    float ang = (-6.2831855f * (float)j) / 8192.0f;
    float s, c;
    sincosf(ang, &s, &c);
    float opr = 1.0f + c, opi = s;
    float omr = 1.0f - c, omi = -s;
    float inv_p2 = 1.0f / (opr * opr + opi * opi);
    float qr = (omr * opr + omi * opi) * inv_p2;
    float qi = (omi * opr - omr * opi) * inv_p2;
    float gsc = 2.0f / st;
    float gr = gsc * qr, gi = gsc * qi;
    float cr = 2.0f * opr * inv_p2, ci = -2.0f * opi * inv_p2;

    float k00r = 0.f, k00i = 0.f, k01r = 0.f, k01i = 0.f;
    float k10r = 0.f, k10i = 0.f, k11r = 0.f, k11i = 0.f;
#pragma unroll 8
    for (int n = 0; n < NSTATE; n++) {
        float dr = gr - lr[n];
        float di = gi - li[n];
        float inv = 1.0f / (dr * dr + di * di);
        float ir = dr * inv, ii = -di * inv;
        float b = Bp[n], p = Pp[n], ct = Cp[n];
        float v00 = ct * b, v01 = ct * p, v10 = p * b, v11 = p * p;
        k00r += v00 * ir; k00i += v00 * ii;
        k01r += v01 * ir; k01i += v01 * ii;
        k10r += v10 * ir; k10i += v10 * ii;
        k11r += v11 * ir; k11i += v11 * ii;
    }
    float d1r = 1.0f + k11r, d1i = k11i;
    float invd1 = 1.0f / (d1r * d1r + d1i * d1i);
    float numr = k01r * k10r - k01i * k10i;
    float numi = k01r * k10i + k01i * k10r;
    float qr2 = (numr * d1r + numi * d1i) * invd1;
    float qi2 = (numi * d1r - numr * d1i) * invd1;
    float tr = k00r - qr2, ti = k00i - qi2;
    g_kraw[layer][j] = make_float2(cr * tr - ci * ti, cr * ti + ci * tr);
}

__global__ void symmetrize_k_kernel() {
    int gid = blockIdx.x * blockDim.x + threadIdx.x;
    if (gid >= NLAYERS * FFT_L) return;
    int layer = gid >> 13;
    int j     = gid & (FFT_L - 1);
    float2 K1 = g_kraw[layer][j];
    float2 K2 = g_kraw[layer][(FFT_L - j) & (FFT_L - 1)];
    const float sc = 0.5f / (float)FFT_L;   // Hermitian part * 1/N
    g_ke[layer][j] = make_float2((K1.x + K2.x) * sc, (K1.y - K2.y) * sc);
}

// ---------------- T=0 twiddle+store for layer-0 F1 (butterflies 2t, 2t+1) ----------------
__device__ __forceinline__ void store0_fwd(float4* __restrict__ dst, float2 a[8], float2 b[8],
                                           const float2* __restrict__ s_tw, int t) {
    float4 w01 = *(const float4*)&s_tw[t << 1];
    float2 wA[7], wB[7];
    chain7(make_float2(w01.x, w01.y), wA);
    chain7(make_float2(w01.z, w01.w), wB);
    int Pb = t << 3;
    dst[swp(Pb + 0)] = pack2(a[0],              cmul(a[1], wA[0]));
    dst[swp(Pb + 1)] = pack2(cmul(a[2], wA[1]), cmul(a[3], wA[2]));
    dst[swp(Pb + 2)] = pack2(cmul(a[4], wA[3]), cmul(a[5], wA[4]));
    dst[swp(Pb + 3)] = pack2(cmul(a[6], wA[5]), cmul(a[7], wA[6]));
    dst[swp(Pb + 4)] = pack2(b[0],              cmul(b[1], wB[0]));
    dst[swp(Pb + 5)] = pack2(cmul(b[2], wB[1]), cmul(b[3], wB[2]));
    dst[swp(Pb + 6)] = pack2(cmul(b[4], wB[3]), cmul(b[5], wB[4]));
    dst[swp(Pb + 7)] = pack2(cmul(b[6], wB[5]), cmul(b[7], wB[6]));
}

// ---------------- T=0 dual-butterfly store (butterflies t and t+512) ----------------
template <bool INV>
__device__ __forceinline__ void dual_bfly_store(float4* __restrict__ dst,
                                                float2 ai[8], float2 bi[8],
                                                const float2* __restrict__ s_tw, int t) {
    float2 w1a = s_tw[t], w1b = s_tw[t + 512];
    if (INV) { w1a.y = -w1a.y; w1b.y = -w1b.y; }
    float2 wA[7], wB[7];
    chain7(w1a, wA);
    chain7(w1b, wB);
    int Pa = t << 2;               // pairs for elements 8t .. 8t+7
    dst[swp(Pa + 0)] = pack2(ai[0],              cmul(ai[1], wA[0]));
    dst[swp(Pa + 1)] = pack2(cmul(ai[2], wA[1]), cmul(ai[3], wA[2]));
    dst[swp(Pa + 2)] = pack2(cmul(ai[4], wA[3]), cmul(ai[5], wA[4]));
    dst[swp(Pa + 3)] = pack2(cmul(ai[6], wA[5]), cmul(ai[7], wA[6]));
    int Pb = Pa + 2048;            // pairs for elements 8(t+512) .. +7
    dst[swp(Pb + 0)] = pack2(bi[0],              cmul(bi[1], wB[0]));
    dst[swp(Pb + 1)] = pack2(cmul(bi[2], wB[1]), cmul(bi[3], wB[2]));
    dst[swp(Pb + 2)] = pack2(cmul(bi[4], wB[3]), cmul(bi[5], wB[4]));
    dst[swp(Pb + 3)] = pack2(cmul(bi[6], wB[5]), cmul(bi[7], wB[6]));
}

// ---------------- generic radix-8 pass for T in {3, 6}: shared twiddle chain ----------------
template <bool INV, int T>
__device__ __forceinline__ void r8_pass(const float4* __restrict__ src,
                                        float4* __restrict__ dst,
                                        const float2* __restrict__ s_tw) {
    int t = threadIdx.x;
    float2 a[8], b[8];
#pragma unroll
    for (int j = 0; j < 8; ++j) {
        float4 v = src[swp(t + 512 * j)];
        a[j] = make_float2(v.x, v.y);
        b[j] = make_float2(v.z, v.w);
    }
    dft8<INV>(a);
    dft8<INV>(b);
    int idx = t << 1;
    int pT = idx & ~((1 << T) - 1);
    int qA = idx & ((1 << T) - 1);
    float2 w1 = s_tw[pT];
    if (INV) w1.y = -w1.y;
    float2 w[7];
    chain7(w1, w);
    int Pb = (qA >> 1) + (pT << 2);
    const int S = 1 << (T - 1);
    dst[swp(Pb + 0 * S)] = pack2(a[0], b[0]);
    dst[swp(Pb + 1 * S)] = pack2(cmul(a[1], w[0]), cmul(b[1], w[0]));
    dst[swp(Pb + 2 * S)] = pack2(cmul(a[2], w[1]), cmul(b[2], w[1]));
    dst[swp(Pb + 3 * S)] = pack2(cmul(a[3], w[2]), cmul(b[3], w[2]));
    dst[swp(Pb + 4 * S)] = pack2(cmul(a[4], w[3]), cmul(b[4], w[3]));
    dst[swp(Pb + 5 * S)] = pack2(cmul(a[5], w[4]), cmul(b[5], w[4]));
    dst[swp(Pb + 6 * S)] = pack2(cmul(a[6], w[5]), cmul(b[6], w[5]));
    dst[swp(Pb + 7 * S)] = pack2(cmul(a[7], w[6]), cmul(b[7], w[6]));
}

// ---------------- fused 4-layer block kernel ----------------
__global__ void __launch_bounds__(THREADS, 1)
ssm_block_kernel(const float* __restrict__ in, float* __restrict__ out) {
    extern __shared__ float4 smem4[];
    float4* X4 = smem4;             // 4096 pairs, swizzled
    float4* Y4 = smem4 + 4096;      // 4096 pairs, swizzled
    float4* U4 = smem4 + 8192;      // current layer input (residual), plain pair layout
    float2* s_tw = (float2*)(smem4 + 12288);   // 1024-entry twiddle cache (8 KB)

    size_t row = (size_t)blockIdx.x * 2;
    const float* in0 = in + row * FFT_L;
    const float* in1 = in + (row + 1) * FFT_L;
    float* o0 = out + row * FFT_L;
    float* o1 = out + (row + 1) * FFT_L;
    int t = threadIdx.x;

    // cache g_tw[0..1024) in smem: thread t writes entries 2t, 2t+1.
    *(float4*)&s_tw[t << 1] = *(const float4*)&g_tw[t << 1];

    // ---- layer-0 F1: radix-8 (T=0) from gmem; stash residual pairs in U ----
    {
        float2 a[8], b[8];
#pragma unroll
        for (int j = 0; j < 8; ++j) {
            int i = (t << 1) + 1024 * j;
            float2 va = *(const float2*)(in0 + i);
            float2 vb = *(const float2*)(in1 + i);
            a[j] = make_float2(va.x, vb.x);
            b[j] = make_float2(va.y, vb.y);
            U4[t + 512 * j] = make_float4(va.x, vb.x, va.y, vb.y);
        }
        dft8<false>(a);
        dft8<false>(b);
        store0_fwd(X4, a, b, s_tw, t);
    }
    __syncthreads();

    for (int layer = 0; layer < NLAYERS; ++layer) {
        r8_pass<false, 3>(X4, Y4, s_tw); __syncthreads();
        r8_pass<false, 6>(Y4, X4, s_tw); __syncthreads();

        // ---- MID: F4 (radix-16) -> filter -> I1 (two inverse radix-8, T=0), X -> Y ----
        {
            const float2* Xs = (const float2*)X4;
            const float2* __restrict__ ke = g_ke[layer];
            float2 a[16], S[16];
#pragma unroll
            for (int j = 0; j < 16; ++j) a[j] = ld_elem(Xs, t + (j << 9));
            dft16<false>(a, S);
#pragma unroll
            for (int k = 0; k < 16; ++k) S[k] = cmul(S[k], ke[t + (k << 9)]);
            float2 ai[8], bi[8];
#pragma unroll
            for (int j = 0; j < 8; ++j) {
                ai[j] = S[2 * j];
                bi[j] = S[2 * j + 1];
            }
            dft8<true>(ai);
            dft8<true>(bi);
            dual_bfly_store<true>(Y4, ai, bi, s_tw, t);
        }
        __syncthreads();

        r8_pass<true, 3>(Y4, X4, s_tw); __syncthreads();
        r8_pass<true, 6>(X4, Y4, s_tw); __syncthreads();

        if (layer < NLAYERS - 1) {
            // ---- BOUNDARY: I4 (radix-16 inv) + residual/GELU (U r/w) + next F1, Y -> X ----
            const float2* Ys = (const float2*)Y4;
            float2* Ue = (float2*)U4;
            float2 a[16], Xo[16];
#pragma unroll
            for (int j = 0; j < 16; ++j) a[j] = ld_elem(Ys, t + (j << 9));
            dft16<true>(a, Xo);
            GeluC gc = gelu_consts();
            float2 v[16];
#pragma unroll
            for (int k = 0; k < 16; ++k) {
                int i = t + (k << 9);
                float2 u = Ue[i];                    // same thread wrote element i
                v[k] = gelu2(cadd(Xo[k], u), gc);
                Ue[i] = v[k];                        // next layer's residual
            }
            float2 ai[8], bi[8];
#pragma unroll
            for (int j = 0; j < 8; ++j) {
                ai[j] = v[2 * j];
                bi[j] = v[2 * j + 1];
            }
            dft8<false>(ai);
            dft8<false>(bi);
            dual_bfly_store<false>(X4, ai, bi, s_tw, t);
            __syncthreads();
        } else {
            // ---- final I4: radix-16 inv + residual + GELU -> gmem ----
            const float2* Ys = (const float2*)Y4;
            const float2* Ue = (const float2*)U4;
            float2 a[16], Xo[16];
#pragma unroll
            for (int j = 0; j < 16; ++j) a[j] = ld_elem(Ys, t + (j << 9));
            dft16<true>(a, Xo);
            GeluC gc = gelu_consts();
#pragma unroll
            for (int k = 0; k < 16; ++k) {
                int i = t + (k << 9);
                float2 res = gelu2(cadd(Xo[k], Ue[i]), gc);
                o0[i] = res.x;
                o1[i] = res.y;
            }
        }
    }
}

// ---------------- launch ----------------
extern "C" void kernel_launch(void* const* d_in, const int* in_sizes, int n_in,
                              void* d_out, int out_size) {
    const float* u  = (const float*)d_in[0];
    const float* Lr = (const float*)d_in[1];
    const float* Li = (const float*)d_in[2];
    const float* P  = (const float*)d_in[3];
    const float* B  = (const float*)d_in[4];
    const float* Ct = (const float*)d_in[5];
    const float* st = (const float*)d_in[6];
    float* out = (float*)d_out;

    const size_t smem_bytes = 3 * 4096 * sizeof(float4) + 1024 * sizeof(float2);   // 200 KB
    cudaFuncSetAttribute(ssm_block_kernel,
                         cudaFuncAttributeMaxDynamicSharedMemorySize, (int)smem_bytes);

    init_tw_kernel<<<FFT_L / 256, 256>>>();
    compute_k_kernel<<<(NLAYERS * FFT_L) / 256, 256>>>(Lr, Li, P, B, Ct, st);
    symmetrize_k_kernel<<<(NLAYERS * FFT_L) / 256, 256>>>();

    ssm_block_kernel<<<NROWS / 2, THREADS, smem_bytes>>>(u, out);
}